// round 11
// baseline (speedup 1.0000x reference)
#include <cuda_runtime.h>

// ---------------------------------------------------------------------------
// stripe_post: column scans + 98-tap guided filter + diff scan.
// M=2048, N=4096, coarse rows MCR=683, hX stride 4.
// Outputs (concatenated): b_adpt, diff, diff_adpt, b  (each M*N f32).
//
// Structure (10 kernels, float4-vectorized, two-level scans):
//   decay_part/scan : coarse column cumsum (683 rows)
//   b_part          : per-8-row partial sums of b*sp(w)
//   pscan(g_pb)     : exclusive prefix over the 256 partials  (~4us)
//   main            : fused scan + fusion -> b, b_adpt, x  (O(1) prefix)
//   vbox_x          : vertical 98-tap sums of x, x^2          (box1 part 1)
//   hAB   (row krn) : hbox -> A,bb -> hbox of A,bb            (box1 p2+box2 p1)
//   vbox_diff       : vertical 98-tap -> diff, inc, 8-row partials (box2 p2)
//   pscan(g_pD)     : exclusive prefix over the 256 partials
//   dscan           : cumsum(inc) -> diff_adpt, finalize b_adpt
// ---------------------------------------------------------------------------

static constexpr int M      = 2048;
static constexpr int NC     = 4096;
static constexpr int NC4    = 1024;              // NC/4
static constexpr int MCR    = 683;
static constexpr int SEG_S  = 8;                 // fine column-scan segment
static constexpr int NSEG_S = 256;
static constexpr int SEG_C  = 32;                // coarse decay segment
static constexpr int NSEG_C = 22;                // ceil(683/32)
static constexpr int SEG_V  = 16;                // vertical-box segment
static constexpr int NSEG_V = 128;
static constexpr int SEG_D  = 8;                 // dscan segment
static constexpr int NSEG_D = 256;
static constexpr int PADL   = 48;
static constexpr int PADR   = 49;
static constexpr int TAPS   = 98;                // 2*r taps per axis
static constexpr int SMW    = NC + PADL + PADR;  // 4193
static constexpr int HCH    = 9;                 // hAB per-thread chunk (coprime 32)
static constexpr float BOXNORM = 1.0f / 9604.0f; // 1/(98*98)
static constexpr float CSC = 683.0f / 2048.0f;   // resize inv_scale

#define PLANE (M * NC)

// Scratch (static device globals: no allocation allowed)
__device__ float g_x [PLANE];
__device__ float g_t1[PLANE];   // vbox(x) sums; later reused as inc plane
__device__ float g_t2[PLANE];   // vbox(x^2) sums
__device__ float g_t3[PLANE];   // hbox(A)
__device__ float g_t4[PLANE];   // hbox(bb)
__device__ float g_Dc[MCR * NC];
__device__ float g_pb[NSEG_S * NC];
__device__ float g_pd[NSEG_C * NC];
__device__ float g_pD[NSEG_D * NC];

// ---- float4 helpers -------------------------------------------------------
__device__ __forceinline__ float4 ld4(const float* p, int i4) {
    return reinterpret_cast<const float4*>(p)[i4];
}
__device__ __forceinline__ void st4(float* p, int i4, float4 v) {
    reinterpret_cast<float4*>(p)[i4] = v;
}
__device__ __forceinline__ float4 operator+(float4 a, float4 b) {
    return make_float4(a.x+b.x, a.y+b.y, a.z+b.z, a.w+b.w);
}
__device__ __forceinline__ float4 operator-(float4 a, float4 b) {
    return make_float4(a.x-b.x, a.y-b.y, a.z-b.z, a.w-b.w);
}
__device__ __forceinline__ float4 operator*(float4 a, float4 b) {
    return make_float4(a.x*b.x, a.y*b.y, a.z*b.z, a.w*b.w);
}
__device__ __forceinline__ float4 operator*(float s, float4 b) {
    return make_float4(s*b.x, s*b.y, s*b.z, s*b.w);
}
__device__ __forceinline__ float4 operator-(float s, float4 b) {
    return make_float4(s-b.x, s-b.y, s-b.z, s-b.w);
}
__device__ __forceinline__ float4 f4zero() { return make_float4(0.f,0.f,0.f,0.f); }
__device__ __forceinline__ float4 max4(float4 a, float s) {
    return make_float4(fmaxf(a.x,s), fmaxf(a.y,s), fmaxf(a.z,s), fmaxf(a.w,s));
}

__device__ __forceinline__ float softplusf(float x) {
    // tolerance is 1e-3; fast intrinsics are ~1e-7 absolute here
    return fmaxf(x, 0.0f) + __logf(1.0f + __expf(-fabsf(x)));
}
__device__ __forceinline__ float4 sp4(float4 v) {
    return make_float4(softplusf(v.x), softplusf(v.y),
                       softplusf(v.z), softplusf(v.w));
}

// ---------------------------------------------------------------------------
// Exclusive prefix over segment partials, in place. One thread per 4 columns;
// sequential independent L2 loads -> cheap (partials plane is L2-resident).
// ---------------------------------------------------------------------------
__global__ __launch_bounds__(256) void k_pscan(float* __restrict__ p, int nseg)
{
    int c4 = blockIdx.x * 256 + threadIdx.x;
    float4 run = f4zero();
    #pragma unroll 8
    for (int s = 0; s < nseg; ++s) {
        int i4 = s * NC4 + c4;
        float4 v = ld4(p, i4);
        st4(p, i4, run);
        run = run + v;
    }
}

// ---------------------------------------------------------------------------
// Stage 0: decay coarse cumsum (2-pass segmented column scan over 683 rows)
// ---------------------------------------------------------------------------
__global__ __launch_bounds__(256) void k_decay_part(
    const float* __restrict__ bneg, const float* __restrict__ dcol)
{
    int c4  = blockIdx.x * 256 + threadIdx.x;
    int seg = blockIdx.y;
    int k0 = seg * SEG_C;
    int k1 = min(MCR, k0 + SEG_C);
    float4 s = f4zero();
    #pragma unroll 4
    for (int k = k0; k < k1; ++k) {
        int i4 = k * NC4 + c4;
        s = s + ld4(bneg, i4) * sp4(ld4(dcol, i4));
    }
    st4(g_pd, seg * NC4 + c4, s);
}

__global__ __launch_bounds__(256) void k_decay_scan(
    const float* __restrict__ bneg, const float* __restrict__ dcol)
{
    int c4  = blockIdx.x * 256 + threadIdx.x;
    int seg = blockIdx.y;
    float4 run = f4zero();
    #pragma unroll 4
    for (int s = 0; s < seg; ++s) run = run + ld4(g_pd, s * NC4 + c4);
    int k0 = seg * SEG_C;
    int k1 = min(MCR, k0 + SEG_C);
    for (int k = k0; k < k1; ++k) {
        int i4 = k * NC4 + c4;
        run = run + ld4(bneg, i4) * sp4(ld4(dcol, i4));
        st4(g_Dc, i4, run);
    }
}

// ---------------------------------------------------------------------------
// Stage 1: b per-segment partials; prefix via k_pscan; fused main scan:
//   b_full = cumsum(b*sp(w)) + decay_lerp*(1-fg)
//   b_adpt = b_full*fm + b_old*(1-fm);  x = hX[4i] + b_adpt - recon
// ---------------------------------------------------------------------------
__global__ __launch_bounds__(256) void k_b_part(
    const float* __restrict__ b, const float* __restrict__ w)
{
    int c4  = blockIdx.x * 256 + threadIdx.x;
    int seg = blockIdx.y;
    int i0 = seg * SEG_S;
    float4 s = f4zero();
    #pragma unroll
    for (int i = i0; i < i0 + SEG_S; ++i) {
        int i4 = i * NC4 + c4;
        s = s + ld4(b, i4) * sp4(ld4(w, i4));
    }
    st4(g_pb, seg * NC4 + c4, s);
}

__global__ __launch_bounds__(256, 5) void k_main(
    const float* __restrict__ b,     const float* __restrict__ w,
    const float* __restrict__ fg,    const float* __restrict__ hX,
    const float* __restrict__ recon, const float* __restrict__ fmask,
    const float* __restrict__ bold,
    float* __restrict__ o_badpt, float* __restrict__ o_b)
{
    int c4  = blockIdx.x * 256 + threadIdx.x;
    int seg = blockIdx.y;
    float4 run = ld4(g_pb, seg * NC4 + c4);   // exclusive prefix, O(1)
    int i0 = seg * SEG_S;

    #pragma unroll
    for (int i = i0; i < i0 + SEG_S; ++i) {
        int i4 = i * NC4 + c4;
        run = run + ld4(b, i4) * sp4(ld4(w, i4));

        float sf = fminf(fmaxf((i + 0.5f) * CSC - 0.5f, 0.0f), 682.0f);
        int kk = min((int)sf, 681);
        float f = sf - (float)kk;
        float4 D0 = ld4(g_Dc, kk * NC4 + c4);
        float4 D1 = ld4(g_Dc, (kk + 1) * NC4 + c4);
        float4 decay = D0 + f * (D1 - D0);

        float4 bfull = run + decay * (1.0f - ld4(fg, i4));
        float4 fmv = ld4(fmask, i4);
        float4 badpt = bfull * fmv + ld4(bold, i4) * (1.0f - fmv);

        st4(o_b, i4, bfull);
        st4(o_badpt, i4, badpt);   // pre-subtraction; finalized in k_dscan
        st4(g_x, i4, ld4(hX, (i << 2) * NC4 + c4) + badpt - ld4(recon, i4));
    }
}

// ---------------------------------------------------------------------------
// Vertical 98-tap sums of x and x^2 (rows [i-48, i+49], replicate clamp).
// Thread-per-4-columns sliding window over SEG_V rows. box1 part 1.
// ---------------------------------------------------------------------------
template <bool CLAMP>
__device__ __forceinline__ void vbox_x_body(int c4, int r0)
{
    float4 s1 = f4zero(), s2 = f4zero();
    #pragma unroll 2
    for (int k = r0 - PADL; k <= r0 + PADR; ++k) {
        int kc = CLAMP ? min(max(k, 0), M - 1) : k;
        float4 v = ld4(g_x, kc * NC4 + c4);
        s1 = s1 + v; s2 = s2 + v * v;
    }
    #pragma unroll 4
    for (int i = r0; i < r0 + SEG_V; ++i) {
        st4(g_t1, i * NC4 + c4, s1);
        st4(g_t2, i * NC4 + c4, s2);
        int ka = CLAMP ? min(i + PADR + 1, M - 1) : i + PADR + 1;
        int kr = CLAMP ? max(i - PADL, 0)         : i - PADL;
        float4 va = ld4(g_x, ka * NC4 + c4);
        float4 vr = ld4(g_x, kr * NC4 + c4);
        s1 = s1 + va - vr;
        s2 = s2 + va * va - vr * vr;
    }
}

__global__ __launch_bounds__(256) void k_vbox_x()
{
    int c4 = blockIdx.x * 256 + threadIdx.x;
    int r0 = blockIdx.y * SEG_V;
    if (blockIdx.y < 4 || blockIdx.y >= NSEG_V - 4) vbox_x_body<true >(c4, r0);
    else                                            vbox_x_body<false>(c4, r0);
}

// ---------------------------------------------------------------------------
// Row kernel: hbox of (v1,v2) -> mean,mean2 -> A,bb pointwise -> hbox of A,bb.
// One block per row, 512 threads, chunk 9 (coprime with 32 -> conflict-free
// LDS). All window work in smem; outputs staged for coalesced stores.
// ---------------------------------------------------------------------------
__global__ __launch_bounds__(512) void k_hAB()
{
    extern __shared__ float sm[];
    float* sv1 = sm;                 // SMW  (vbox sums of x;   staging out A2)
    float* sv2 = sv1 + SMW;          // SMW  (vbox sums of x^2; staging out bb2)
    float* sA  = sv2 + SMW;          // SMW
    float* sB  = sA + SMW;           // SMW
    int row = blockIdx.x, tid = threadIdx.x;

    const float* r1 = g_t1 + row * NC;
    const float* r2 = g_t2 + row * NC;
    for (int j = tid; j < NC; j += 512) { sv1[PADL + j] = r1[j]; sv2[PADL + j] = r2[j]; }
    if (tid < PADL)             { sv1[tid] = r1[0];           sv2[tid] = r2[0]; }
    else if (tid < PADL + PADR) { sv1[NC + tid] = r1[NC - 1]; sv2[NC + tid] = r2[NC - 1]; }
    __syncthreads();

    int base = tid * HCH;
    int cnt  = (base < NC) ? min(HCH, NC - base) : 0;

    // pass 1: window sums of v1,v2 -> A,bb per column
    if (cnt) {
        float s1 = 0.0f, s2 = 0.0f;
        #pragma unroll 14
        for (int u = 0; u < TAPS; ++u) { s1 += sv1[base + u]; s2 += sv2[base + u]; }
        for (int j = 0; ; ) {
            float mean  = s1 * BOXNORM;
            float mean2 = s2 * BOXNORM;
            float var = mean2 - mean * mean;
            float A = var / (var + 1.0f);       // eps = 1
            sA[PADL + base + j] = A;
            sB[PADL + base + j] = mean - A * mean;
            if (++j >= cnt) break;
            s1 += sv1[base + j + TAPS - 1] - sv1[base + j - 1];
            s2 += sv2[base + j + TAPS - 1] - sv2[base + j - 1];
        }
    }
    __syncthreads();
    if (tid < PADL)             { sA[tid] = sA[PADL];               sB[tid] = sB[PADL]; }
    else if (tid < PADL + PADR) { sA[NC + tid] = sA[PADL + NC - 1]; sB[NC + tid] = sB[PADL + NC - 1]; }
    __syncthreads();

    // pass 2: window sums of A,bb -> staged in sv1,sv2 (dead after pass 1)
    if (cnt) {
        float sa = 0.0f, sb = 0.0f;
        #pragma unroll 14
        for (int u = 0; u < TAPS; ++u) { sa += sA[base + u]; sb += sB[base + u]; }
        sv1[base] = sa; sv2[base] = sb;
        for (int j = 1; j < cnt; ++j) {
            sa += sA[base + j + TAPS - 1] - sA[base + j - 1];
            sb += sB[base + j + TAPS - 1] - sB[base + j - 1];
            sv1[base + j] = sa; sv2[base + j] = sb;
        }
    }
    __syncthreads();
    for (int j = tid; j < NC; j += 512) {
        g_t3[row * NC + j] = sv1[j];
        g_t4[row * NC + j] = sv2[j];
    }
}

// ---------------------------------------------------------------------------
// Final vertical 98-tap of hA,hbb + diff + fused diff-scan prep:
//   diff = A2*x + bb2 ; inc = max(diff[i]-diff[i-1],0)*sp(ww) -> g_t1
//   per-8-row partials of inc -> g_pD (2 per 16-row segment)
// ---------------------------------------------------------------------------
template <bool CLAMP>
__device__ __forceinline__ void vbox_diff_body(
    int c4, int r0, int seg, const float* __restrict__ ww,
    float* __restrict__ o_diff)
{
    int ibeg = CLAMP ? max(r0 - 1, 0) : r0 - 1;
    float4 s1 = f4zero(), s2 = f4zero();
    #pragma unroll 2
    for (int k = ibeg - PADL; k <= ibeg + PADR; ++k) {
        int kc = CLAMP ? min(max(k, 0), M - 1) : k;
        s1 = s1 + ld4(g_t3, kc * NC4 + c4);
        s2 = s2 + ld4(g_t4, kc * NC4 + c4);
    }
    float4 prev = f4zero(), acc = f4zero(), half = f4zero();
    #pragma unroll 2
    for (int i = ibeg; i < r0 + SEG_V; ++i) {
        int i4 = i * NC4 + c4;
        float4 dv = (BOXNORM * s1) * ld4(g_x, i4) + BOXNORM * s2;
        if (i < r0) {
            prev = dv;                           // warm-up row (r0-1)
        } else {
            if (CLAMP && i == 0) prev = dv;      // prepend: inc[0] = 0
            float4 ic = max4(dv - prev, 0.0f) * sp4(ld4(ww, i4));
            st4(o_diff, i4, dv);
            st4(g_t1, i4, ic);                   // inc plane (t1 reused)
            acc = acc + ic;
            prev = dv;
            if (i == r0 + SEG_D - 1) half = acc; // first 8-row partial
        }
        int ka = CLAMP ? min(i + PADR + 1, M - 1) : i + PADR + 1;
        int kr = CLAMP ? max(i - PADL, 0)         : i - PADL;
        s1 = s1 + ld4(g_t3, ka * NC4 + c4) - ld4(g_t3, kr * NC4 + c4);
        s2 = s2 + ld4(g_t4, ka * NC4 + c4) - ld4(g_t4, kr * NC4 + c4);
    }
    st4(g_pD, (2 * seg    ) * NC4 + c4, half);
    st4(g_pD, (2 * seg + 1) * NC4 + c4, acc - half);
}

__global__ __launch_bounds__(256) void k_vbox_diff(
    const float* __restrict__ ww, float* __restrict__ o_diff)
{
    int c4 = blockIdx.x * 256 + threadIdx.x;
    int seg = blockIdx.y;
    int r0 = seg * SEG_V;
    if (seg < 4 || seg >= NSEG_V - 4) vbox_diff_body<true >(c4, r0, seg, ww, o_diff);
    else                              vbox_diff_body<false>(c4, r0, seg, ww, o_diff);
}

// ---------------------------------------------------------------------------
// Stage 6: diff_adpt = cumsum(inc); b_adpt -= diff_adpt  (O(1) prefix)
// ---------------------------------------------------------------------------
__global__ __launch_bounds__(256) void k_dscan(
    float* __restrict__ o_dadpt, float* __restrict__ o_badpt)
{
    int c4  = blockIdx.x * 256 + threadIdx.x;
    int seg = blockIdx.y;
    float4 cum = ld4(g_pD, seg * NC4 + c4);   // exclusive prefix
    int i0 = seg * SEG_D;
    #pragma unroll
    for (int i = i0; i < i0 + SEG_D; ++i) {
        int i4 = i * NC4 + c4;
        cum = cum + ld4(g_t1, i4);
        st4(o_dadpt, i4, cum);
        st4(o_badpt, i4, ld4(o_badpt, i4) - cum);   // finalize b_adpt
    }
}

// ---------------------------------------------------------------------------
extern "C" void kernel_launch(void* const* d_in, const int* in_sizes, int n_in,
                              void* d_out, int out_size)
{
    (void)in_sizes; (void)n_in; (void)out_size;
    const float* b     = (const float*)d_in[0];
    const float* bneg  = (const float*)d_in[1];
    const float* fg    = (const float*)d_in[2];
    const float* hX    = (const float*)d_in[3];
    const float* recon = (const float*)d_in[4];
    const float* fmask = (const float*)d_in[5];
    const float* bold  = (const float*)d_in[6];
    // d_in[7] = r (int32 scalar, value 4; hX stride hardcoded)
    const float* w     = (const float*)d_in[8];
    const float* dcol  = (const float*)d_in[9];
    const float* ww    = (const float*)d_in[10];

    float* out     = (float*)d_out;
    float* o_badpt = out;
    float* o_diff  = out + (size_t)PLANE;
    float* o_dadpt = out + 2 * (size_t)PLANE;
    float* o_b     = out + 3 * (size_t)PLANE;

    // k_hAB needs 4*SMW*4 = 67088 B smem -> dynamic + opt-in
    int hab_smem = 4 * SMW * (int)sizeof(float);
    cudaFuncSetAttribute(k_hAB, cudaFuncAttributeMaxDynamicSharedMemorySize,
                         hab_smem);

    dim3 gC(NC4 / 256, NSEG_C);   // (4, 22)
    dim3 gS(NC4 / 256, NSEG_S);   // (4, 256)
    dim3 gV(NC4 / 256, NSEG_V);   // (4, 128)
    dim3 gD(NC4 / 256, NSEG_D);   // (4, 256)

    float* pb_ptr; cudaGetSymbolAddress((void**)&pb_ptr, g_pb);
    float* pD_ptr; cudaGetSymbolAddress((void**)&pD_ptr, g_pD);

    k_decay_part<<<gC, 256>>>(bneg, dcol);
    k_decay_scan<<<gC, 256>>>(bneg, dcol);
    k_b_part    <<<gS, 256>>>(b, w);
    k_pscan     <<<NC4 / 256, 256>>>(pb_ptr, NSEG_S);
    k_main      <<<gS, 256>>>(b, w, fg, hX, recon, fmask, bold, o_badpt, o_b);
    k_vbox_x    <<<gV, 256>>>();
    k_hAB       <<<M, 512, hab_smem>>>();
    k_vbox_diff <<<gV, 256>>>(ww, o_diff);
    k_pscan     <<<NC4 / 256, 256>>>(pD_ptr, NSEG_D);
    k_dscan     <<<gD, 256>>>(o_dadpt, o_badpt);
}

// round 12
// speedup vs baseline: 1.1392x; 1.1392x over previous
#include <cuda_runtime.h>

// ---------------------------------------------------------------------------
// stripe_post: column scans + 98-tap guided filter + diff scan.
// M=2048, N=4096, coarse rows MCR=683, hX stride 4.
// Outputs (concatenated): b_adpt, diff, diff_adpt, b  (each M*N f32).
//
// Structure (10 kernels, float4-vectorized, two-level scans):
//   decay_part/scan : coarse column cumsum (683 rows)
//   b_part          : per-8-row partial sums of b*sp(w)
//   pscan(g_pb)     : warp-parallel exclusive prefix over 256 partials (~6us)
//   main            : fused scan + fusion -> b, b_adpt, x  (O(1) prefix)
//   vbox_x          : vertical 98-tap sums of x, x^2          (box1 part 1)
//   hAB   (row krn) : hbox -> A,bb -> hbox of A,bb            (box1 p2+box2 p1)
//   vbox_diff       : vertical 98-tap -> diff, inc, 8-row partials (box2 p2)
//   pscan(g_pD)     : warp-parallel exclusive prefix over 256 partials
//   dscan           : cumsum(inc) -> diff_adpt, finalize b_adpt
// ---------------------------------------------------------------------------

static constexpr int M      = 2048;
static constexpr int NC     = 4096;
static constexpr int NC4    = 1024;              // NC/4
static constexpr int MCR    = 683;
static constexpr int SEG_S  = 8;                 // fine column-scan segment
static constexpr int NSEG_S = 256;
static constexpr int SEG_C  = 32;                // coarse decay segment
static constexpr int NSEG_C = 22;                // ceil(683/32)
static constexpr int SEG_V  = 16;                // vertical-box segment
static constexpr int NSEG_V = 128;
static constexpr int SEG_D  = 8;                 // dscan segment
static constexpr int NSEG_D = 256;
static constexpr int PADL   = 48;
static constexpr int PADR   = 49;
static constexpr int TAPS   = 98;                // 2*r taps per axis
static constexpr int SMW    = NC + PADL + PADR;  // 4193
static constexpr int HCH    = 9;                 // hAB per-thread chunk (coprime 32)
static constexpr float BOXNORM = 1.0f / 9604.0f; // 1/(98*98)
static constexpr float CSC = 683.0f / 2048.0f;   // resize inv_scale

#define PLANE (M * NC)

// Scratch (static device globals: no allocation allowed)
__device__ float g_x [PLANE];
__device__ float g_t1[PLANE];   // vbox(x) sums; later reused as inc plane
__device__ float g_t2[PLANE];   // vbox(x^2) sums
__device__ float g_t3[PLANE];   // hbox(A)
__device__ float g_t4[PLANE];   // hbox(bb)
__device__ float g_Dc[MCR * NC];
__device__ float g_pb[NSEG_S * NC];
__device__ float g_pd[NSEG_C * NC];
__device__ float g_pD[NSEG_D * NC];

// ---- float4 helpers -------------------------------------------------------
__device__ __forceinline__ float4 ld4(const float* p, int i4) {
    return reinterpret_cast<const float4*>(p)[i4];
}
__device__ __forceinline__ void st4(float* p, int i4, float4 v) {
    reinterpret_cast<float4*>(p)[i4] = v;
}
__device__ __forceinline__ float4 operator+(float4 a, float4 b) {
    return make_float4(a.x+b.x, a.y+b.y, a.z+b.z, a.w+b.w);
}
__device__ __forceinline__ float4 operator-(float4 a, float4 b) {
    return make_float4(a.x-b.x, a.y-b.y, a.z-b.z, a.w-b.w);
}
__device__ __forceinline__ float4 operator*(float4 a, float4 b) {
    return make_float4(a.x*b.x, a.y*b.y, a.z*b.z, a.w*b.w);
}
__device__ __forceinline__ float4 operator*(float s, float4 b) {
    return make_float4(s*b.x, s*b.y, s*b.z, s*b.w);
}
__device__ __forceinline__ float4 operator-(float s, float4 b) {
    return make_float4(s-b.x, s-b.y, s-b.z, s-b.w);
}
__device__ __forceinline__ float4 f4zero() { return make_float4(0.f,0.f,0.f,0.f); }
__device__ __forceinline__ float4 max4(float4 a, float s) {
    return make_float4(fmaxf(a.x,s), fmaxf(a.y,s), fmaxf(a.z,s), fmaxf(a.w,s));
}

__device__ __forceinline__ float softplusf(float x) {
    // tolerance is 1e-3; fast intrinsics are ~1e-7 absolute here
    return fmaxf(x, 0.0f) + __logf(1.0f + __expf(-fabsf(x)));
}
__device__ __forceinline__ float4 sp4(float4 v) {
    return make_float4(softplusf(v.x), softplusf(v.y),
                       softplusf(v.z), softplusf(v.w));
}

// ---------------------------------------------------------------------------
// Warp-parallel in-place exclusive prefix over 256 segment partials.
// Block = 256 threads handles 16 float4-columns: thread (col, g) owns the
// 16-segment group g of column col. Group threads are 16 consecutive lanes
// -> width-16 shfl scan combines group sums. Grid = 64 blocks (64 SMs).
// ---------------------------------------------------------------------------
__global__ __launch_bounds__(256) void k_pscan256(float* __restrict__ p)
{
    int col    = threadIdx.x >> 4;          // 0..15 within block
    int grp    = threadIdx.x & 15;          // segment group 0..15
    int c4     = blockIdx.x * 16 + col;
    int s0     = grp * 16;

    // group sum (16 independent loads)
    float4 s = f4zero();
    #pragma unroll
    for (int k = 0; k < 16; ++k) s = s + ld4(p, (s0 + k) * NC4 + c4);

    // inclusive scan across the 16 group threads (width-16 shfl)
    float4 inc = s;
    #pragma unroll
    for (int d = 1; d < 16; d <<= 1) {
        float vx = __shfl_up_sync(0xffffffffu, inc.x, d, 16);
        float vy = __shfl_up_sync(0xffffffffu, inc.y, d, 16);
        float vz = __shfl_up_sync(0xffffffffu, inc.z, d, 16);
        float vw = __shfl_up_sync(0xffffffffu, inc.w, d, 16);
        if (grp >= d) { inc.x += vx; inc.y += vy; inc.z += vz; inc.w += vw; }
    }
    float4 run = inc - s;                   // exclusive group prefix

    // replay segments, writing exclusive per-segment prefix in place
    #pragma unroll
    for (int k = 0; k < 16; ++k) {
        int i4 = (s0 + k) * NC4 + c4;
        float4 v = ld4(p, i4);
        st4(p, i4, run);
        run = run + v;
    }
}

// ---------------------------------------------------------------------------
// Stage 0: decay coarse cumsum (2-pass segmented column scan over 683 rows)
// ---------------------------------------------------------------------------
__global__ __launch_bounds__(256) void k_decay_part(
    const float* __restrict__ bneg, const float* __restrict__ dcol)
{
    int c4  = blockIdx.x * 256 + threadIdx.x;
    int seg = blockIdx.y;
    int k0 = seg * SEG_C;
    int k1 = min(MCR, k0 + SEG_C);
    float4 s = f4zero();
    #pragma unroll 4
    for (int k = k0; k < k1; ++k) {
        int i4 = k * NC4 + c4;
        s = s + ld4(bneg, i4) * sp4(ld4(dcol, i4));
    }
    st4(g_pd, seg * NC4 + c4, s);
}

__global__ __launch_bounds__(256) void k_decay_scan(
    const float* __restrict__ bneg, const float* __restrict__ dcol)
{
    int c4  = blockIdx.x * 256 + threadIdx.x;
    int seg = blockIdx.y;
    float4 run = f4zero();
    #pragma unroll 4
    for (int s = 0; s < seg; ++s) run = run + ld4(g_pd, s * NC4 + c4);
    int k0 = seg * SEG_C;
    int k1 = min(MCR, k0 + SEG_C);
    for (int k = k0; k < k1; ++k) {
        int i4 = k * NC4 + c4;
        run = run + ld4(bneg, i4) * sp4(ld4(dcol, i4));
        st4(g_Dc, i4, run);
    }
}

// ---------------------------------------------------------------------------
// Stage 1: b per-segment partials; prefix via k_pscan256; fused main scan:
//   b_full = cumsum(b*sp(w)) + decay_lerp*(1-fg)
//   b_adpt = b_full*fm + b_old*(1-fm);  x = hX[4i] + b_adpt - recon
// ---------------------------------------------------------------------------
__global__ __launch_bounds__(256) void k_b_part(
    const float* __restrict__ b, const float* __restrict__ w)
{
    int c4  = blockIdx.x * 256 + threadIdx.x;
    int seg = blockIdx.y;
    int i0 = seg * SEG_S;
    float4 s = f4zero();
    #pragma unroll
    for (int i = i0; i < i0 + SEG_S; ++i) {
        int i4 = i * NC4 + c4;
        s = s + ld4(b, i4) * sp4(ld4(w, i4));
    }
    st4(g_pb, seg * NC4 + c4, s);
}

__global__ __launch_bounds__(256, 5) void k_main(
    const float* __restrict__ b,     const float* __restrict__ w,
    const float* __restrict__ fg,    const float* __restrict__ hX,
    const float* __restrict__ recon, const float* __restrict__ fmask,
    const float* __restrict__ bold,
    float* __restrict__ o_badpt, float* __restrict__ o_b)
{
    int c4  = blockIdx.x * 256 + threadIdx.x;
    int seg = blockIdx.y;
    float4 run = ld4(g_pb, seg * NC4 + c4);   // exclusive prefix, O(1)
    int i0 = seg * SEG_S;

    #pragma unroll
    for (int i = i0; i < i0 + SEG_S; ++i) {
        int i4 = i * NC4 + c4;
        run = run + ld4(b, i4) * sp4(ld4(w, i4));

        float sf = fminf(fmaxf((i + 0.5f) * CSC - 0.5f, 0.0f), 682.0f);
        int kk = min((int)sf, 681);
        float f = sf - (float)kk;
        float4 D0 = ld4(g_Dc, kk * NC4 + c4);
        float4 D1 = ld4(g_Dc, (kk + 1) * NC4 + c4);
        float4 decay = D0 + f * (D1 - D0);

        float4 bfull = run + decay * (1.0f - ld4(fg, i4));
        float4 fmv = ld4(fmask, i4);
        float4 badpt = bfull * fmv + ld4(bold, i4) * (1.0f - fmv);

        st4(o_b, i4, bfull);
        st4(o_badpt, i4, badpt);   // pre-subtraction; finalized in k_dscan
        st4(g_x, i4, ld4(hX, (i << 2) * NC4 + c4) + badpt - ld4(recon, i4));
    }
}

// ---------------------------------------------------------------------------
// Vertical 98-tap sums of x and x^2 (rows [i-48, i+49], replicate clamp).
// Thread-per-4-columns sliding window over SEG_V rows. box1 part 1.
// ---------------------------------------------------------------------------
template <bool CLAMP>
__device__ __forceinline__ void vbox_x_body(int c4, int r0)
{
    float4 s1 = f4zero(), s2 = f4zero();
    #pragma unroll 2
    for (int k = r0 - PADL; k <= r0 + PADR; ++k) {
        int kc = CLAMP ? min(max(k, 0), M - 1) : k;
        float4 v = ld4(g_x, kc * NC4 + c4);
        s1 = s1 + v; s2 = s2 + v * v;
    }
    #pragma unroll 4
    for (int i = r0; i < r0 + SEG_V; ++i) {
        st4(g_t1, i * NC4 + c4, s1);
        st4(g_t2, i * NC4 + c4, s2);
        int ka = CLAMP ? min(i + PADR + 1, M - 1) : i + PADR + 1;
        int kr = CLAMP ? max(i - PADL, 0)         : i - PADL;
        float4 va = ld4(g_x, ka * NC4 + c4);
        float4 vr = ld4(g_x, kr * NC4 + c4);
        s1 = s1 + va - vr;
        s2 = s2 + va * va - vr * vr;
    }
}

__global__ __launch_bounds__(256) void k_vbox_x()
{
    int c4 = blockIdx.x * 256 + threadIdx.x;
    int r0 = blockIdx.y * SEG_V;
    if (blockIdx.y < 4 || blockIdx.y >= NSEG_V - 4) vbox_x_body<true >(c4, r0);
    else                                            vbox_x_body<false>(c4, r0);
}

// ---------------------------------------------------------------------------
// Row kernel: hbox of (v1,v2) -> mean,mean2 -> A,bb pointwise -> hbox of A,bb.
// One block per row, 512 threads, chunk 9 (coprime with 32 -> conflict-free
// LDS). All window work in smem; outputs staged for coalesced stores.
// ---------------------------------------------------------------------------
__global__ __launch_bounds__(512) void k_hAB()
{
    extern __shared__ float sm[];
    float* sv1 = sm;                 // SMW  (vbox sums of x;   staging out A2)
    float* sv2 = sv1 + SMW;          // SMW  (vbox sums of x^2; staging out bb2)
    float* sA  = sv2 + SMW;          // SMW
    float* sB  = sA + SMW;           // SMW
    int row = blockIdx.x, tid = threadIdx.x;

    const float* r1 = g_t1 + row * NC;
    const float* r2 = g_t2 + row * NC;
    for (int j = tid; j < NC; j += 512) { sv1[PADL + j] = r1[j]; sv2[PADL + j] = r2[j]; }
    if (tid < PADL)             { sv1[tid] = r1[0];           sv2[tid] = r2[0]; }
    else if (tid < PADL + PADR) { sv1[NC + tid] = r1[NC - 1]; sv2[NC + tid] = r2[NC - 1]; }
    __syncthreads();

    int base = tid * HCH;
    int cnt  = (base < NC) ? min(HCH, NC - base) : 0;

    // pass 1: window sums of v1,v2 -> A,bb per column
    if (cnt) {
        float s1 = 0.0f, s2 = 0.0f;
        #pragma unroll 14
        for (int u = 0; u < TAPS; ++u) { s1 += sv1[base + u]; s2 += sv2[base + u]; }
        for (int j = 0; ; ) {
            float mean  = s1 * BOXNORM;
            float mean2 = s2 * BOXNORM;
            float var = mean2 - mean * mean;
            float A = var / (var + 1.0f);       // eps = 1
            sA[PADL + base + j] = A;
            sB[PADL + base + j] = mean - A * mean;
            if (++j >= cnt) break;
            s1 += sv1[base + j + TAPS - 1] - sv1[base + j - 1];
            s2 += sv2[base + j + TAPS - 1] - sv2[base + j - 1];
        }
    }
    __syncthreads();
    if (tid < PADL)             { sA[tid] = sA[PADL];               sB[tid] = sB[PADL]; }
    else if (tid < PADL + PADR) { sA[NC + tid] = sA[PADL + NC - 1]; sB[NC + tid] = sB[PADL + NC - 1]; }
    __syncthreads();

    // pass 2: window sums of A,bb -> staged in sv1,sv2 (dead after pass 1)
    if (cnt) {
        float sa = 0.0f, sb = 0.0f;
        #pragma unroll 14
        for (int u = 0; u < TAPS; ++u) { sa += sA[base + u]; sb += sB[base + u]; }
        sv1[base] = sa; sv2[base] = sb;
        for (int j = 1; j < cnt; ++j) {
            sa += sA[base + j + TAPS - 1] - sA[base + j - 1];
            sb += sB[base + j + TAPS - 1] - sB[base + j - 1];
            sv1[base + j] = sa; sv2[base + j] = sb;
        }
    }
    __syncthreads();
    for (int j = tid; j < NC; j += 512) {
        g_t3[row * NC + j] = sv1[j];
        g_t4[row * NC + j] = sv2[j];
    }
}

// ---------------------------------------------------------------------------
// Final vertical 98-tap of hA,hbb + diff + fused diff-scan prep:
//   diff = A2*x + bb2 ; inc = max(diff[i]-diff[i-1],0)*sp(ww) -> g_t1
//   per-8-row partials of inc -> g_pD (2 per 16-row segment)
// ---------------------------------------------------------------------------
template <bool CLAMP>
__device__ __forceinline__ void vbox_diff_body(
    int c4, int r0, int seg, const float* __restrict__ ww,
    float* __restrict__ o_diff)
{
    int ibeg = CLAMP ? max(r0 - 1, 0) : r0 - 1;
    float4 s1 = f4zero(), s2 = f4zero();
    #pragma unroll 2
    for (int k = ibeg - PADL; k <= ibeg + PADR; ++k) {
        int kc = CLAMP ? min(max(k, 0), M - 1) : k;
        s1 = s1 + ld4(g_t3, kc * NC4 + c4);
        s2 = s2 + ld4(g_t4, kc * NC4 + c4);
    }
    float4 prev = f4zero(), acc = f4zero(), half = f4zero();
    #pragma unroll 2
    for (int i = ibeg; i < r0 + SEG_V; ++i) {
        int i4 = i * NC4 + c4;
        float4 dv = (BOXNORM * s1) * ld4(g_x, i4) + BOXNORM * s2;
        if (i < r0) {
            prev = dv;                           // warm-up row (r0-1)
        } else {
            if (CLAMP && i == 0) prev = dv;      // prepend: inc[0] = 0
            float4 ic = max4(dv - prev, 0.0f) * sp4(ld4(ww, i4));
            st4(o_diff, i4, dv);
            st4(g_t1, i4, ic);                   // inc plane (t1 reused)
            acc = acc + ic;
            prev = dv;
            if (i == r0 + SEG_D - 1) half = acc; // first 8-row partial
        }
        int ka = CLAMP ? min(i + PADR + 1, M - 1) : i + PADR + 1;
        int kr = CLAMP ? max(i - PADL, 0)         : i - PADL;
        s1 = s1 + ld4(g_t3, ka * NC4 + c4) - ld4(g_t3, kr * NC4 + c4);
        s2 = s2 + ld4(g_t4, ka * NC4 + c4) - ld4(g_t4, kr * NC4 + c4);
    }
    st4(g_pD, (2 * seg    ) * NC4 + c4, half);
    st4(g_pD, (2 * seg + 1) * NC4 + c4, acc - half);
}

__global__ __launch_bounds__(256) void k_vbox_diff(
    const float* __restrict__ ww, float* __restrict__ o_diff)
{
    int c4 = blockIdx.x * 256 + threadIdx.x;
    int seg = blockIdx.y;
    int r0 = seg * SEG_V;
    if (seg < 4 || seg >= NSEG_V - 4) vbox_diff_body<true >(c4, r0, seg, ww, o_diff);
    else                              vbox_diff_body<false>(c4, r0, seg, ww, o_diff);
}

// ---------------------------------------------------------------------------
// Stage 6: diff_adpt = cumsum(inc); b_adpt -= diff_adpt  (O(1) prefix)
// ---------------------------------------------------------------------------
__global__ __launch_bounds__(256) void k_dscan(
    float* __restrict__ o_dadpt, float* __restrict__ o_badpt)
{
    int c4  = blockIdx.x * 256 + threadIdx.x;
    int seg = blockIdx.y;
    float4 cum = ld4(g_pD, seg * NC4 + c4);   // exclusive prefix
    int i0 = seg * SEG_D;
    #pragma unroll
    for (int i = i0; i < i0 + SEG_D; ++i) {
        int i4 = i * NC4 + c4;
        cum = cum + ld4(g_t1, i4);
        st4(o_dadpt, i4, cum);
        st4(o_badpt, i4, ld4(o_badpt, i4) - cum);   // finalize b_adpt
    }
}

// ---------------------------------------------------------------------------
extern "C" void kernel_launch(void* const* d_in, const int* in_sizes, int n_in,
                              void* d_out, int out_size)
{
    (void)in_sizes; (void)n_in; (void)out_size;
    const float* b     = (const float*)d_in[0];
    const float* bneg  = (const float*)d_in[1];
    const float* fg    = (const float*)d_in[2];
    const float* hX    = (const float*)d_in[3];
    const float* recon = (const float*)d_in[4];
    const float* fmask = (const float*)d_in[5];
    const float* bold  = (const float*)d_in[6];
    // d_in[7] = r (int32 scalar, value 4; hX stride hardcoded)
    const float* w     = (const float*)d_in[8];
    const float* dcol  = (const float*)d_in[9];
    const float* ww    = (const float*)d_in[10];

    float* out     = (float*)d_out;
    float* o_badpt = out;
    float* o_diff  = out + (size_t)PLANE;
    float* o_dadpt = out + 2 * (size_t)PLANE;
    float* o_b     = out + 3 * (size_t)PLANE;

    // k_hAB needs 4*SMW*4 = 67088 B smem -> dynamic + opt-in
    int hab_smem = 4 * SMW * (int)sizeof(float);
    cudaFuncSetAttribute(k_hAB, cudaFuncAttributeMaxDynamicSharedMemorySize,
                         hab_smem);

    dim3 gC(NC4 / 256, NSEG_C);   // (4, 22)
    dim3 gS(NC4 / 256, NSEG_S);   // (4, 256)
    dim3 gV(NC4 / 256, NSEG_V);   // (4, 128)
    dim3 gD(NC4 / 256, NSEG_D);   // (4, 256)

    float* pb_ptr; cudaGetSymbolAddress((void**)&pb_ptr, g_pb);
    float* pD_ptr; cudaGetSymbolAddress((void**)&pD_ptr, g_pD);

    k_decay_part<<<gC, 256>>>(bneg, dcol);
    k_decay_scan<<<gC, 256>>>(bneg, dcol);
    k_b_part    <<<gS, 256>>>(b, w);
    k_pscan256  <<<NC4 / 16, 256>>>(pb_ptr);
    k_main      <<<gS, 256>>>(b, w, fg, hX, recon, fmask, bold, o_badpt, o_b);
    k_vbox_x    <<<gV, 256>>>();
    k_hAB       <<<M, 512, hab_smem>>>();
    k_vbox_diff <<<gV, 256>>>(ww, o_diff);
    k_pscan256  <<<NC4 / 16, 256>>>(pD_ptr);
    k_dscan     <<<gD, 256>>>(o_dadpt, o_badpt);
}

// round 17
// speedup vs baseline: 1.2681x; 1.1132x over previous
#include <cuda_runtime.h>

// ---------------------------------------------------------------------------
// stripe_post: column scans + 98-tap guided filter + diff scan.
// M=2048, N=4096, coarse rows MCR=683, hX stride 4.
// Outputs (concatenated): b_adpt, diff, diff_adpt, b  (each M*N f32).
//
// Structure (10 kernels, float4-vectorized, two-level scans):
//   decay_part/scan : coarse column cumsum (683 rows)
//   b_part          : per-8-row partial sums of b*sp(w)
//   pscan(g_pb)     : warp-parallel exclusive prefix over 256 partials (~5us)
//   main            : fused scan + fusion -> b, b_adpt, x  (O(1) prefix)
//   vbox_x          : vertical 98-tap sums of x, x^2          (box1 part 1)
//   hAB   (row krn) : hbox -> A,bb -> hbox of A,bb            (box1 p2+box2 p1)
//   vbox_diff       : vertical 98-tap -> diff, inc, 8-row partials (box2 p2)
//   pscan(g_pD)     : warp-parallel exclusive prefix over 256 partials
//   dscan           : cumsum(inc) -> diff_adpt, finalize b_adpt
// ---------------------------------------------------------------------------

static constexpr int M      = 2048;
static constexpr int NC     = 4096;
static constexpr int NC4    = 1024;              // NC/4
static constexpr int MCR    = 683;
static constexpr int SEG_S  = 8;                 // fine column-scan segment
static constexpr int NSEG_S = 256;
static constexpr int SEG_C  = 32;                // coarse decay segment
static constexpr int NSEG_C = 22;                // ceil(683/32)
static constexpr int SEG_V  = 16;                // vertical-box segment
static constexpr int NSEG_V = 128;
static constexpr int SEG_D  = 8;                 // dscan segment
static constexpr int NSEG_D = 256;
static constexpr int PADL   = 48;
static constexpr int PADR   = 49;
static constexpr int TAPS   = 98;                // 2*r taps per axis
static constexpr int SMW    = NC + PADL + PADR;  // 4193 (logical row width)
static constexpr int SMWP   = 4196;              // padded stride, multiple of 4
                                                 // -> every smem plane 16B-aligned
static constexpr int HCH    = 17;                // hAB chunk (coprime 32 -> no conflicts)
static constexpr float BOXNORM = 1.0f / 9604.0f; // 1/(98*98)
static constexpr float CSC = 683.0f / 2048.0f;   // resize inv_scale

#define PLANE (M * NC)

// Scratch (static device globals: no allocation allowed)
__device__ float g_x [PLANE];
__device__ float g_t1[PLANE];   // vbox(x) sums; later reused as inc plane
__device__ float g_t2[PLANE];   // vbox(x^2) sums
__device__ float g_t3[PLANE];   // hbox(A)
__device__ float g_t4[PLANE];   // hbox(bb)
__device__ float g_Dc[MCR * NC];
__device__ float g_pb[NSEG_S * NC];
__device__ float g_pd[NSEG_C * NC];
__device__ float g_pD[NSEG_D * NC];

// ---- float4 helpers -------------------------------------------------------
__device__ __forceinline__ float4 ld4(const float* p, int i4) {
    return reinterpret_cast<const float4*>(p)[i4];
}
__device__ __forceinline__ void st4(float* p, int i4, float4 v) {
    reinterpret_cast<float4*>(p)[i4] = v;
}
__device__ __forceinline__ float4 operator+(float4 a, float4 b) {
    return make_float4(a.x+b.x, a.y+b.y, a.z+b.z, a.w+b.w);
}
__device__ __forceinline__ float4 operator-(float4 a, float4 b) {
    return make_float4(a.x-b.x, a.y-b.y, a.z-b.z, a.w-b.w);
}
__device__ __forceinline__ float4 operator*(float4 a, float4 b) {
    return make_float4(a.x*b.x, a.y*b.y, a.z*b.z, a.w*b.w);
}
__device__ __forceinline__ float4 operator*(float s, float4 b) {
    return make_float4(s*b.x, s*b.y, s*b.z, s*b.w);
}
__device__ __forceinline__ float4 operator-(float s, float4 b) {
    return make_float4(s-b.x, s-b.y, s-b.z, s-b.w);
}
__device__ __forceinline__ float4 f4zero() { return make_float4(0.f,0.f,0.f,0.f); }
__device__ __forceinline__ float4 max4(float4 a, float s) {
    return make_float4(fmaxf(a.x,s), fmaxf(a.y,s), fmaxf(a.z,s), fmaxf(a.w,s));
}

__device__ __forceinline__ float softplusf(float x) {
    // tolerance is 1e-3; fast intrinsics are ~1e-7 absolute here
    return fmaxf(x, 0.0f) + __logf(1.0f + __expf(-fabsf(x)));
}
__device__ __forceinline__ float4 sp4(float4 v) {
    return make_float4(softplusf(v.x), softplusf(v.y),
                       softplusf(v.z), softplusf(v.w));
}

// ---------------------------------------------------------------------------
// Warp-parallel in-place exclusive prefix over 256 segment partials.
// Block = 256 threads = 8 float4-columns x 32 segment-groups (8 segments
// each). Group threads are a full warp per column -> width-32 shfl scan.
// Grid = 128 blocks.
// ---------------------------------------------------------------------------
__global__ __launch_bounds__(256) void k_pscan256(float* __restrict__ p)
{
    int col = threadIdx.x >> 5;             // 0..7 within block
    int grp = threadIdx.x & 31;             // segment group 0..31
    int c4  = blockIdx.x * 8 + col;
    int s0  = grp * 8;

    // group sum (8 independent loads)
    float4 s = f4zero();
    #pragma unroll
    for (int k = 0; k < 8; ++k) s = s + ld4(p, (s0 + k) * NC4 + c4);

    // inclusive scan across the 32 group threads
    float4 inc = s;
    #pragma unroll
    for (int d = 1; d < 32; d <<= 1) {
        float vx = __shfl_up_sync(0xffffffffu, inc.x, d, 32);
        float vy = __shfl_up_sync(0xffffffffu, inc.y, d, 32);
        float vz = __shfl_up_sync(0xffffffffu, inc.z, d, 32);
        float vw = __shfl_up_sync(0xffffffffu, inc.w, d, 32);
        if (grp >= d) { inc.x += vx; inc.y += vy; inc.z += vz; inc.w += vw; }
    }
    float4 run = inc - s;                   // exclusive group prefix

    // replay segments, writing exclusive per-segment prefix in place
    #pragma unroll
    for (int k = 0; k < 8; ++k) {
        int i4 = (s0 + k) * NC4 + c4;
        float4 v = ld4(p, i4);
        st4(p, i4, run);
        run = run + v;
    }
}

// ---------------------------------------------------------------------------
// Stage 0: decay coarse cumsum (2-pass segmented column scan over 683 rows)
// ---------------------------------------------------------------------------
__global__ __launch_bounds__(256) void k_decay_part(
    const float* __restrict__ bneg, const float* __restrict__ dcol)
{
    int c4  = blockIdx.x * 256 + threadIdx.x;
    int seg = blockIdx.y;
    int k0 = seg * SEG_C;
    int k1 = min(MCR, k0 + SEG_C);
    float4 s = f4zero();
    #pragma unroll 4
    for (int k = k0; k < k1; ++k) {
        int i4 = k * NC4 + c4;
        s = s + ld4(bneg, i4) * sp4(ld4(dcol, i4));
    }
    st4(g_pd, seg * NC4 + c4, s);
}

__global__ __launch_bounds__(256) void k_decay_scan(
    const float* __restrict__ bneg, const float* __restrict__ dcol)
{
    int c4  = blockIdx.x * 256 + threadIdx.x;
    int seg = blockIdx.y;
    float4 run = f4zero();
    #pragma unroll 4
    for (int s = 0; s < seg; ++s) run = run + ld4(g_pd, s * NC4 + c4);
    int k0 = seg * SEG_C;
    int k1 = min(MCR, k0 + SEG_C);
    for (int k = k0; k < k1; ++k) {
        int i4 = k * NC4 + c4;
        run = run + ld4(bneg, i4) * sp4(ld4(dcol, i4));
        st4(g_Dc, i4, run);
    }
}

// ---------------------------------------------------------------------------
// Stage 1: b per-segment partials; prefix via k_pscan256; fused main scan:
//   b_full = cumsum(b*sp(w)) + decay_lerp*(1-fg)
//   b_adpt = b_full*fm + b_old*(1-fm);  x = hX[4i] + b_adpt - recon
// ---------------------------------------------------------------------------
__global__ __launch_bounds__(256) void k_b_part(
    const float* __restrict__ b, const float* __restrict__ w)
{
    int c4  = blockIdx.x * 256 + threadIdx.x;
    int seg = blockIdx.y;
    int i0 = seg * SEG_S;
    float4 s = f4zero();
    #pragma unroll
    for (int i = i0; i < i0 + SEG_S; ++i) {
        int i4 = i * NC4 + c4;
        s = s + ld4(b, i4) * sp4(ld4(w, i4));
    }
    st4(g_pb, seg * NC4 + c4, s);
}

__global__ __launch_bounds__(256, 5) void k_main(
    const float* __restrict__ b,     const float* __restrict__ w,
    const float* __restrict__ fg,    const float* __restrict__ hX,
    const float* __restrict__ recon, const float* __restrict__ fmask,
    const float* __restrict__ bold,
    float* __restrict__ o_badpt, float* __restrict__ o_b)
{
    int c4  = blockIdx.x * 256 + threadIdx.x;
    int seg = blockIdx.y;
    float4 run = ld4(g_pb, seg * NC4 + c4);   // exclusive prefix, O(1)
    int i0 = seg * SEG_S;

    #pragma unroll
    for (int i = i0; i < i0 + SEG_S; ++i) {
        int i4 = i * NC4 + c4;
        run = run + ld4(b, i4) * sp4(ld4(w, i4));

        float sf = fminf(fmaxf((i + 0.5f) * CSC - 0.5f, 0.0f), 682.0f);
        int kk = min((int)sf, 681);
        float f = sf - (float)kk;
        float4 D0 = ld4(g_Dc, kk * NC4 + c4);
        float4 D1 = ld4(g_Dc, (kk + 1) * NC4 + c4);
        float4 decay = D0 + f * (D1 - D0);

        float4 bfull = run + decay * (1.0f - ld4(fg, i4));
        float4 fmv = ld4(fmask, i4);
        float4 badpt = bfull * fmv + ld4(bold, i4) * (1.0f - fmv);

        st4(o_b, i4, bfull);
        st4(o_badpt, i4, badpt);   // pre-subtraction; finalized in k_dscan
        st4(g_x, i4, ld4(hX, (i << 2) * NC4 + c4) + badpt - ld4(recon, i4));
    }
}

// ---------------------------------------------------------------------------
// Vertical 98-tap sums of x and x^2 (rows [i-48, i+49], replicate clamp).
// Thread-per-4-columns sliding window over SEG_V rows. box1 part 1.
// ---------------------------------------------------------------------------
template <bool CLAMP>
__device__ __forceinline__ void vbox_x_body(int c4, int r0)
{
    float4 s1 = f4zero(), s2 = f4zero();
    #pragma unroll 2
    for (int k = r0 - PADL; k <= r0 + PADR; ++k) {
        int kc = CLAMP ? min(max(k, 0), M - 1) : k;
        float4 v = ld4(g_x, kc * NC4 + c4);
        s1 = s1 + v; s2 = s2 + v * v;
    }
    #pragma unroll 4
    for (int i = r0; i < r0 + SEG_V; ++i) {
        st4(g_t1, i * NC4 + c4, s1);
        st4(g_t2, i * NC4 + c4, s2);
        int ka = CLAMP ? min(i + PADR + 1, M - 1) : i + PADR + 1;
        int kr = CLAMP ? max(i - PADL, 0)         : i - PADL;
        float4 va = ld4(g_x, ka * NC4 + c4);
        float4 vr = ld4(g_x, kr * NC4 + c4);
        s1 = s1 + va - vr;
        s2 = s2 + va * va - vr * vr;
    }
}

__global__ __launch_bounds__(256) void k_vbox_x()
{
    int c4 = blockIdx.x * 256 + threadIdx.x;
    int r0 = blockIdx.y * SEG_V;
    if (blockIdx.y < 4 || blockIdx.y >= NSEG_V - 4) vbox_x_body<true >(c4, r0);
    else                                            vbox_x_body<false>(c4, r0);
}

// ---------------------------------------------------------------------------
// Row kernel: hbox of (v1,v2) -> mean,mean2 -> A,bb pointwise -> hbox of A,bb.
// One block per row, 512 threads, chunk 17 (coprime with 32 -> conflict-free
// LDS; 241 active threads in window phases). All window work in smem;
// float4 global load/store phases. Plane stride SMWP (mult of 4) keeps all
// four smem planes 16B-aligned.
// ---------------------------------------------------------------------------
__global__ __launch_bounds__(512) void k_hAB()
{
    extern __shared__ float sm[];
    float* sv1 = sm;                 // SMWP (vbox sums of x;   staging out A2)
    float* sv2 = sv1 + SMWP;         // SMWP (vbox sums of x^2; staging out bb2)
    float* sA  = sv2 + SMWP;         // SMWP
    float* sB  = sA + SMWP;          // SMWP
    int row = blockIdx.x, tid = threadIdx.x;

    const float* r1 = g_t1 + row * NC;
    const float* r2 = g_t2 + row * NC;
    // PADL = 48 floats = 12 float4 -> aligned smem float4 stores
    for (int j4 = tid; j4 < NC4; j4 += 512) {
        reinterpret_cast<float4*>(sv1 + PADL)[j4] = ld4(r1, j4);
        reinterpret_cast<float4*>(sv2 + PADL)[j4] = ld4(r2, j4);
    }
    if (tid < PADL)             { sv1[tid] = r1[0];           sv2[tid] = r2[0]; }
    else if (tid < PADL + PADR) { sv1[NC + tid] = r1[NC - 1]; sv2[NC + tid] = r2[NC - 1]; }
    __syncthreads();

    int base = tid * HCH;
    int cnt  = (base < NC) ? min(HCH, NC - base) : 0;

    // pass 1: window sums of v1,v2 -> A,bb per column
    if (cnt) {
        float s1 = 0.0f, s2 = 0.0f;
        #pragma unroll 14
        for (int u = 0; u < TAPS; ++u) { s1 += sv1[base + u]; s2 += sv2[base + u]; }
        for (int j = 0; ; ) {
            float mean  = s1 * BOXNORM;
            float mean2 = s2 * BOXNORM;
            float var = mean2 - mean * mean;
            float A = var / (var + 1.0f);       // eps = 1
            sA[PADL + base + j] = A;
            sB[PADL + base + j] = mean - A * mean;
            if (++j >= cnt) break;
            s1 += sv1[base + j + TAPS - 1] - sv1[base + j - 1];
            s2 += sv2[base + j + TAPS - 1] - sv2[base + j - 1];
        }
    }
    __syncthreads();
    if (tid < PADL)             { sA[tid] = sA[PADL];               sB[tid] = sB[PADL]; }
    else if (tid < PADL + PADR) { sA[NC + tid] = sA[PADL + NC - 1]; sB[NC + tid] = sB[PADL + NC - 1]; }
    __syncthreads();

    // pass 2: window sums of A,bb -> staged in sv1,sv2 (dead after pass 1)
    if (cnt) {
        float sa = 0.0f, sb = 0.0f;
        #pragma unroll 14
        for (int u = 0; u < TAPS; ++u) { sa += sA[base + u]; sb += sB[base + u]; }
        sv1[base] = sa; sv2[base] = sb;
        for (int j = 1; j < cnt; ++j) {
            sa += sA[base + j + TAPS - 1] - sA[base + j - 1];
            sb += sB[base + j + TAPS - 1] - sB[base + j - 1];
            sv1[base + j] = sa; sv2[base + j] = sb;
        }
    }
    __syncthreads();
    for (int j4 = tid; j4 < NC4; j4 += 512) {
        st4(g_t3 + row * NC, j4, reinterpret_cast<const float4*>(sv1)[j4]);
        st4(g_t4 + row * NC, j4, reinterpret_cast<const float4*>(sv2)[j4]);
    }
}

// ---------------------------------------------------------------------------
// Final vertical 98-tap of hA,hbb + diff + fused diff-scan prep:
//   diff = A2*x + bb2 ; inc = max(diff[i]-diff[i-1],0)*sp(ww) -> g_t1
//   per-8-row partials of inc -> g_pD (2 per 16-row segment)
// ---------------------------------------------------------------------------
template <bool CLAMP>
__device__ __forceinline__ void vbox_diff_body(
    int c4, int r0, int seg, const float* __restrict__ ww,
    float* __restrict__ o_diff)
{
    int ibeg = CLAMP ? max(r0 - 1, 0) : r0 - 1;
    float4 s1 = f4zero(), s2 = f4zero();
    #pragma unroll 2
    for (int k = ibeg - PADL; k <= ibeg + PADR; ++k) {
        int kc = CLAMP ? min(max(k, 0), M - 1) : k;
        s1 = s1 + ld4(g_t3, kc * NC4 + c4);
        s2 = s2 + ld4(g_t4, kc * NC4 + c4);
    }
    float4 prev = f4zero(), acc = f4zero(), half = f4zero();
    #pragma unroll 2
    for (int i = ibeg; i < r0 + SEG_V; ++i) {
        int i4 = i * NC4 + c4;
        float4 dv = (BOXNORM * s1) * ld4(g_x, i4) + BOXNORM * s2;
        if (i < r0) {
            prev = dv;                           // warm-up row (r0-1)
        } else {
            if (CLAMP && i == 0) prev = dv;      // prepend: inc[0] = 0
            float4 ic = max4(dv - prev, 0.0f) * sp4(ld4(ww, i4));
            st4(o_diff, i4, dv);
            st4(g_t1, i4, ic);                   // inc plane (t1 reused)
            acc = acc + ic;
            prev = dv;
            if (i == r0 + SEG_D - 1) half = acc; // first 8-row partial
        }
        int ka = CLAMP ? min(i + PADR + 1, M - 1) : i + PADR + 1;
        int kr = CLAMP ? max(i - PADL, 0)         : i - PADL;
        s1 = s1 + ld4(g_t3, ka * NC4 + c4) - ld4(g_t3, kr * NC4 + c4);
        s2 = s2 + ld4(g_t4, ka * NC4 + c4) - ld4(g_t4, kr * NC4 + c4);
    }
    st4(g_pD, (2 * seg    ) * NC4 + c4, half);
    st4(g_pD, (2 * seg + 1) * NC4 + c4, acc - half);
}

__global__ __launch_bounds__(256) void k_vbox_diff(
    const float* __restrict__ ww, float* __restrict__ o_diff)
{
    int c4 = blockIdx.x * 256 + threadIdx.x;
    int seg = blockIdx.y;
    int r0 = seg * SEG_V;
    if (seg < 4 || seg >= NSEG_V - 4) vbox_diff_body<true >(c4, r0, seg, ww, o_diff);
    else                              vbox_diff_body<false>(c4, r0, seg, ww, o_diff);
}

// ---------------------------------------------------------------------------
// Stage 6: diff_adpt = cumsum(inc); b_adpt -= diff_adpt  (O(1) prefix)
// ---------------------------------------------------------------------------
__global__ __launch_bounds__(256) void k_dscan(
    float* __restrict__ o_dadpt, float* __restrict__ o_badpt)
{
    int c4  = blockIdx.x * 256 + threadIdx.x;
    int seg = blockIdx.y;
    float4 cum = ld4(g_pD, seg * NC4 + c4);   // exclusive prefix
    int i0 = seg * SEG_D;
    #pragma unroll
    for (int i = i0; i < i0 + SEG_D; ++i) {
        int i4 = i * NC4 + c4;
        cum = cum + ld4(g_t1, i4);
        st4(o_dadpt, i4, cum);
        st4(o_badpt, i4, ld4(o_badpt, i4) - cum);   // finalize b_adpt
    }
}

// ---------------------------------------------------------------------------
extern "C" void kernel_launch(void* const* d_in, const int* in_sizes, int n_in,
                              void* d_out, int out_size)
{
    (void)in_sizes; (void)n_in; (void)out_size;
    const float* b     = (const float*)d_in[0];
    const float* bneg  = (const float*)d_in[1];
    const float* fg    = (const float*)d_in[2];
    const float* hX    = (const float*)d_in[3];
    const float* recon = (const float*)d_in[4];
    const float* fmask = (const float*)d_in[5];
    const float* bold  = (const float*)d_in[6];
    // d_in[7] = r (int32 scalar, value 4; hX stride hardcoded)
    const float* w     = (const float*)d_in[8];
    const float* dcol  = (const float*)d_in[9];
    const float* ww    = (const float*)d_in[10];

    float* out     = (float*)d_out;
    float* o_badpt = out;
    float* o_diff  = out + (size_t)PLANE;
    float* o_dadpt = out + 2 * (size_t)PLANE;
    float* o_b     = out + 3 * (size_t)PLANE;

    // k_hAB needs 4*SMWP*4 = 67136 B smem -> dynamic + opt-in
    int hab_smem = 4 * SMWP * (int)sizeof(float);
    cudaFuncSetAttribute(k_hAB, cudaFuncAttributeMaxDynamicSharedMemorySize,
                         hab_smem);

    dim3 gC(NC4 / 256, NSEG_C);   // (4, 22)
    dim3 gS(NC4 / 256, NSEG_S);   // (4, 256)
    dim3 gV(NC4 / 256, NSEG_V);   // (4, 128)
    dim3 gD(NC4 / 256, NSEG_D);   // (4, 256)

    float* pb_ptr; cudaGetSymbolAddress((void**)&pb_ptr, g_pb);
    float* pD_ptr; cudaGetSymbolAddress((void**)&pD_ptr, g_pD);

    k_decay_part<<<gC, 256>>>(bneg, dcol);
    k_decay_scan<<<gC, 256>>>(bneg, dcol);
    k_b_part    <<<gS, 256>>>(b, w);
    k_pscan256  <<<NC4 / 8, 256>>>(pb_ptr);
    k_main      <<<gS, 256>>>(b, w, fg, hX, recon, fmask, bold, o_badpt, o_b);
    k_vbox_x    <<<gV, 256>>>();
    k_hAB       <<<M, 512, hab_smem>>>();
    k_vbox_diff <<<gV, 256>>>(ww, o_diff);
    k_pscan256  <<<NC4 / 8, 256>>>(pD_ptr);
    k_dscan     <<<gD, 256>>>(o_dadpt, o_badpt);
}